// round 13
// baseline (speedup 1.0000x reference)
#include <cuda_runtime.h>
#include <cuda_fp16.h>
#include <mma.h>
#include <math.h>
#include <cstdint>

using namespace nvcuda;

// ============================================================================
// Pure fp16 WMMA fused MLP + segment sum. 256 threads (8 warps, 255-reg
// budget), GEMM2/GEMM1 warp tile 32x128 (frag:MMA = 0.625), N-chunks of 256,
// cp.async single-sync pipelined loops, W3 double-buffered.
//   kernA: H1 = relu(X@W1+b1) -> g_H1 (fp16)
//   kernB: per 256-col chunk: H2c = relu(H1@W2+b2) -> Ps fp16,
//          Y += H2c @ W3c, then g = silu(Y+b3), sorted segment-sum -> out.
// ============================================================================

#define NODES_PAD (3907 * 128)
#define XS_LD  264              // 256 + 8 pad (fp16 elems)
#define WT_LD  72               // 64 + 8 pad
#define T128E  (128 * WT_LD)    // [128x64] tile elems (18,432 B)
#define T256E  (256 * WT_LD)    // [256x64] tile elems (36,864 B)
#define STGE   (T128E + T256E)  // kernel-B GEMM2 stage elems
#define FB_LD  132              // fbuf fp32 ld

__device__ __align__(16) __half g_W1t[512 * 256];
__device__ __align__(16) __half g_W2t[512 * 512];
__device__ __align__(16) __half g_W3t[128 * 512];
__device__ __align__(16) __half g_H1[(size_t)NODES_PAD * 512];

__device__ __forceinline__ void cpa16(uint32_t dst, const void* src) {
    asm volatile("cp.async.cg.shared.global [%0], [%1], 16;" :: "r"(dst), "l"(src));
}
#define CPA_COMMIT() asm volatile("cp.async.commit_group;" ::: "memory")
#define CPA_WAIT0()  asm volatile("cp.async.wait_group 0;" ::: "memory")

// ---------------- setup: transpose weights to fp16 ----------------
__global__ void setup_weights(const float* __restrict__ W1, const float* __restrict__ W2,
                              const float* __restrict__ W3)
{
    int i = blockIdx.x * blockDim.x + threadIdx.x;
    if (i < 512 * 256) {
        int n = i >> 8, k = i & 255;
        g_W1t[n * 256 + k] = __float2half_rn(W1[k * 512 + n]);
        return;
    }
    i -= 512 * 256;
    if (i < 512 * 512) {
        int n = i >> 9, k = i & 511;
        g_W2t[n * 512 + k] = __float2half_rn(W2[k * 512 + n]);
        return;
    }
    i -= 512 * 512;
    if (i < 128 * 512) {
        int n = i >> 9, k = i & 511;
        g_W3t[n * 512 + k] = __float2half_rn(W3[k * 128 + n]);
    }
}

__global__ void zero_out_kernel(float* out, int n)
{
    int i = blockIdx.x * blockDim.x + threadIdx.x;
    if (i < n) out[i] = 0.f;
}

// ============================================================================
// Kernel A: H1 = relu(X @ W1 + b1).  256 threads, 2 N-chunks of 256.
// Warp grid 4x2, warp tile 32x128 (acc[2][8]).
// SMEM: Xs [128][264] resident | SW 2 stages x [256][72]  (fbuf aliases SW)
// ============================================================================
__global__ void __launch_bounds__(256, 1)
gemm1_kernel(const float* __restrict__ X, const float* __restrict__ b1, int Nn)
{
    extern __shared__ char smem[];
    __half* Xs = (__half*)smem;                       // 67,584 B
    __half* SW = Xs + 128 * XS_LD;                    // 2 x 36,864 B
    float*  fbuf = (float*)SW;                        // alias (stages idle)
    const uint32_t swu = (uint32_t)__cvta_generic_to_shared(SW);

    const int t   = threadIdx.x;
    const int wid = t >> 5;
    const int wm  = wid & 3;          // 4 warps over M (32 rows each)
    const int wn  = wid >> 2;         // 2 warps over N (128 cols each)
    const int row0 = blockIdx.x * 128;

    // ---- load X (128 x 256 fp32) -> fp16 ----
    #pragma unroll 4
    for (int p = 0; p < 32; ++p) {
        int idx = t + p * 256;
        int r = idx >> 6, c4 = idx & 63;
        float4 v = (row0 + r < Nn) ? *(const float4*)(X + (size_t)(row0 + r) * 256 + c4 * 4)
                                   : make_float4(0.f, 0.f, 0.f, 0.f);
        Xs[r * XS_LD + c4 * 4 + 0] = __float2half_rn(v.x);
        Xs[r * XS_LD + c4 * 4 + 1] = __float2half_rn(v.y);
        Xs[r * XS_LD + c4 * 4 + 2] = __float2half_rn(v.z);
        Xs[r * XS_LD + c4 * 4 + 3] = __float2half_rn(v.w);
    }
    __syncthreads();

    auto prefW = [&](int nc, int kt, int b) {         // W1t tile [256n][64k]
        const uint32_t base = swu + (uint32_t)b * T256E * 2;
        #pragma unroll
        for (int p = 0; p < 8; ++p) {
            int idx = t + p * 256;
            int r = idx >> 3, c8 = idx & 7;
            cpa16(base + (uint32_t)(r * WT_LD + c8 * 8) * 2,
                  g_W1t + (size_t)(nc * 256 + r) * 256 + kt * 64 + c8 * 8);
        }
    };

    for (int nc = 0; nc < 2; ++nc) {
        wmma::fragment<wmma::accumulator, 16, 16, 16, float> acc[2][8];
        #pragma unroll
        for (int i = 0; i < 2; ++i)
            #pragma unroll
            for (int j = 0; j < 8; ++j) wmma::fill_fragment(acc[i][j], 0.f);

        prefW(nc, 0, 0); CPA_COMMIT();
        for (int kt = 0; kt < 4; ++kt) {
            CPA_WAIT0();
            __syncthreads();                          // data kt visible; kt-1 compute done
            if (kt < 3) { prefW(nc, kt + 1, (kt + 1) & 1); CPA_COMMIT(); }
            const __half* Wb = SW + (kt & 1) * T256E;
            #pragma unroll
            for (int ks = 0; ks < 4; ++ks) {
                wmma::fragment<wmma::matrix_a, 16, 16, 16, __half, wmma::row_major> a[2];
                wmma::fragment<wmma::matrix_b, 16, 16, 16, __half, wmma::col_major> b[8];
                #pragma unroll
                for (int i = 0; i < 2; ++i)
                    wmma::load_matrix_sync(a[i], Xs + (wm * 32 + i * 16) * XS_LD + kt * 64 + ks * 16, XS_LD);
                #pragma unroll
                for (int j = 0; j < 8; ++j)
                    wmma::load_matrix_sync(b[j], Wb + (wn * 128 + j * 16) * WT_LD + ks * 16, WT_LD);
                #pragma unroll
                for (int i = 0; i < 2; ++i)
                    #pragma unroll
                    for (int j = 0; j < 8; ++j)
                        wmma::mma_sync(acc[i][j], a[i], b[j], acc[i][j]);
            }
        }
        __syncthreads();                              // all compute done before fbuf (aliases SW)

        // ---- epilogue: two 128-col passes through fbuf ----
        #pragma unroll 1
        for (int h = 0; h < 2; ++h) {
            if (wn == h) {
                #pragma unroll
                for (int i = 0; i < 2; ++i)
                    #pragma unroll
                    for (int j = 0; j < 8; ++j)
                        wmma::store_matrix_sync(fbuf + (wm * 32 + i * 16) * FB_LD + j * 16,
                                                acc[i][j], FB_LD, wmma::mem_row_major);
            }
            __syncthreads();
            int col0 = nc * 256 + h * 128;
            #pragma unroll 4
            for (int p = 0; p < 64; ++p) {
                int idx = t + p * 256;
                int r = idx >> 7, c = idx & 127;
                if (row0 + r < Nn) {
                    float v = fbuf[r * FB_LD + c] + b1[col0 + c];
                    v = v > 0.f ? v : 0.f;
                    g_H1[(size_t)(row0 + r) * 512 + col0 + c] = __float2half_rn(v);
                }
            }
            __syncthreads();
        }
    }
}

// ============================================================================
// Kernel B: H2c = relu(H1@W2+b2); Y += H2c@W3c; silu; segment sum. 256 thr.
// GEMM2 warp tile 32x128 (acc2[2][8]); GEMM3 warp tile 32x64 (Y[2][4]).
// SMEM: SG 2 stages x (Hs [128][72] + W2s [256][72]) | Ps 4 x [128][72] |
//       W3s 2 x [128][72] | gids.  fbuf aliases SG.   Total 221,696 B.
// ============================================================================
__global__ void __launch_bounds__(256, 1)
gemm23_kernel(const int* __restrict__ gidx,
              const float* __restrict__ b2, const float* __restrict__ b3,
              float* __restrict__ out, int Nn)
{
    extern __shared__ char smem[];
    __half* SG  = (__half*)smem;                 // 2 x STGE
    __half* Ps  = SG + 2 * STGE;                 // 4 k-subtiles [128][72]
    __half* W3s = Ps + 4 * T128E;                // 2 bufs [128][72]
    int*    gids = (int*)(W3s + 2 * T128E);
    float*  fbuf = (float*)SG;                   // alias (stages idle)
    const uint32_t sgu = (uint32_t)__cvta_generic_to_shared(SG);
    const uint32_t w3u = (uint32_t)__cvta_generic_to_shared(W3s);

    const int t   = threadIdx.x;
    const int wid = t >> 5;
    const int wm  = wid & 3;
    const int wn  = wid >> 2;                    // 0..1
    const int row0 = blockIdx.x * 128;

    if (t < 128) gids[t] = (row0 + t < Nn) ? gidx[row0 + t] : -1;

    auto prefG2 = [&](int mc, int kt, int b) {
        const uint32_t base = sgu + (uint32_t)b * STGE * 2;
        #pragma unroll
        for (int p = 0; p < 4; ++p) {            // Hs [128][64]
            int idx = t + p * 256;
            int r = idx >> 3, c8 = idx & 7;
            cpa16(base + (uint32_t)(r * WT_LD + c8 * 8) * 2,
                  g_H1 + (size_t)(row0 + r) * 512 + kt * 64 + c8 * 8);
        }
        #pragma unroll
        for (int p = 0; p < 8; ++p) {            // W2s [256][64]
            int idx = t + p * 256;
            int r = idx >> 3, c8 = idx & 7;
            cpa16(base + (uint32_t)T128E * 2 + (uint32_t)(r * WT_LD + c8 * 8) * 2,
                  g_W2t + (size_t)(mc * 256 + r) * 512 + kt * 64 + c8 * 8);
        }
    };
    auto prefW3 = [&](int mc, int kt3, int b) {  // W3t tile [128n][64k]
        const uint32_t base = w3u + (uint32_t)b * T128E * 2;
        #pragma unroll
        for (int p = 0; p < 4; ++p) {
            int idx = t + p * 256;
            int r = idx >> 3, c8 = idx & 7;
            cpa16(base + (uint32_t)(r * WT_LD + c8 * 8) * 2,
                  g_W3t + (size_t)r * 512 + mc * 256 + kt3 * 64 + c8 * 8);
        }
    };

    wmma::fragment<wmma::accumulator, 16, 16, 16, float> Y[2][4];
    #pragma unroll
    for (int i = 0; i < 2; ++i)
        #pragma unroll
        for (int j = 0; j < 4; ++j) wmma::fill_fragment(Y[i][j], 0.f);

    for (int mc = 0; mc < 2; ++mc) {
        wmma::fragment<wmma::accumulator, 16, 16, 16, float> acc2[2][8];
        #pragma unroll
        for (int i = 0; i < 2; ++i)
            #pragma unroll
            for (int j = 0; j < 8; ++j) wmma::fill_fragment(acc2[i][j], 0.f);

        // ---- GEMM2 chunk: single-sync pipelined, kt = 0..7 ----
        prefG2(mc, 0, 0); CPA_COMMIT();
        for (int kt = 0; kt < 8; ++kt) {
            CPA_WAIT0();
            __syncthreads();
            if (kt < 7) { prefG2(mc, kt + 1, (kt + 1) & 1); CPA_COMMIT(); }
            const __half* Hs  = SG + (kt & 1) * STGE;
            const __half* W2s = Hs + T128E;
            #pragma unroll
            for (int ks = 0; ks < 4; ++ks) {
                wmma::fragment<wmma::matrix_a, 16, 16, 16, __half, wmma::row_major> a[2];
                wmma::fragment<wmma::matrix_b, 16, 16, 16, __half, wmma::col_major> b[8];
                #pragma unroll
                for (int i = 0; i < 2; ++i)
                    wmma::load_matrix_sync(a[i], Hs + (wm * 32 + i * 16) * WT_LD + ks * 16, WT_LD);
                #pragma unroll
                for (int j = 0; j < 8; ++j)
                    wmma::load_matrix_sync(b[j], W2s + (wn * 128 + j * 16) * WT_LD + ks * 16, WT_LD);
                #pragma unroll
                for (int i = 0; i < 2; ++i)
                    #pragma unroll
                    for (int j = 0; j < 8; ++j)
                        wmma::mma_sync(acc2[i][j], a[i], b[j], acc2[i][j]);
            }
        }
        prefW3(mc, 0, 0); CPA_COMMIT();          // overlaps chunk epilogue
        __syncthreads();                          // compute done before fbuf (aliases SG)

        // ---- chunk epilogue: two 128-col passes -> Ps (fp16) ----
        #pragma unroll 1
        for (int h = 0; h < 2; ++h) {
            if (wn == h) {
                #pragma unroll
                for (int i = 0; i < 2; ++i)
                    #pragma unroll
                    for (int j = 0; j < 8; ++j)
                        wmma::store_matrix_sync(fbuf + (wm * 32 + i * 16) * FB_LD + j * 16,
                                                acc2[i][j], FB_LD, wmma::mem_row_major);
            }
            __syncthreads();
            #pragma unroll 4
            for (int p = 0; p < 64; ++p) {
                int idx = t + p * 256;
                int r = idx >> 7, c = idx & 127;
                float v = fbuf[r * FB_LD + c] + b2[mc * 256 + h * 128 + c];
                v = v > 0.f ? v : 0.f;
                int sub = h * 2 + (c >> 6);
                Ps[sub * T128E + r * WT_LD + (c & 63)] = __float2half_rn(v);
            }
            __syncthreads();
        }

        // ---- GEMM3 partial: Y += Ps (128x256) @ W3t[:, mc*256..+256] ----
        for (int kt3 = 0; kt3 < 4; ++kt3) {
            CPA_WAIT0();
            __syncthreads();
            if (kt3 < 3) { prefW3(mc, kt3 + 1, (kt3 + 1) & 1); CPA_COMMIT(); }
            const __half* Wb = W3s + (kt3 & 1) * T128E;
            const __half* Pb = Ps + kt3 * T128E;
            #pragma unroll
            for (int ks = 0; ks < 4; ++ks) {
                wmma::fragment<wmma::matrix_a, 16, 16, 16, __half, wmma::row_major> a[2];
                wmma::fragment<wmma::matrix_b, 16, 16, 16, __half, wmma::col_major> b[4];
                #pragma unroll
                for (int i = 0; i < 2; ++i)
                    wmma::load_matrix_sync(a[i], Pb + (wm * 32 + i * 16) * WT_LD + ks * 16, WT_LD);
                #pragma unroll
                for (int j = 0; j < 4; ++j)
                    wmma::load_matrix_sync(b[j], Wb + (wn * 64 + j * 16) * WT_LD + ks * 16, WT_LD);
                #pragma unroll
                for (int i = 0; i < 2; ++i)
                    #pragma unroll
                    for (int j = 0; j < 4; ++j)
                        wmma::mma_sync(Y[i][j], a[i], b[j], Y[i][j]);
            }
        }
        __syncthreads();                          // GEMM3 done before Ps/SG reuse next mc
    }

    // ---- final: Y -> fbuf, +b3, silu, sorted segment reduce, atomics ----
    #pragma unroll
    for (int i = 0; i < 2; ++i)
        #pragma unroll
        for (int j = 0; j < 4; ++j)
            wmma::store_matrix_sync(fbuf + (wm * 32 + i * 16) * FB_LD + wn * 64 + j * 16,
                                    Y[i][j], FB_LD, wmma::mem_row_major);
    __syncthreads();
    #pragma unroll 4
    for (int p = 0; p < 64; ++p) {
        int idx = t + p * 256;
        int r = idx >> 7, c = idx & 127;
        float y = fbuf[r * FB_LD + c] + b3[c];
        fbuf[r * FB_LD + c] = y / (1.f + expf(-y));
    }
    __syncthreads();

    if (t < 128) {
        int cur = gids[0];
        float s = 0.f;
        #pragma unroll 1
        for (int r = 0; r < 128; ++r) {
            int gi = gids[r];
            if (gi != cur) {
                if (cur >= 0) atomicAdd(&out[(size_t)cur * 128 + t], s);
                cur = gi; s = 0.f;
            }
            if (gi >= 0) s += fbuf[r * FB_LD + t];
        }
        if (cur >= 0) atomicAdd(&out[(size_t)cur * 128 + t], s);
    }
}

// ============================================================================
extern "C" void kernel_launch(void* const* d_in, const int* in_sizes, int n_in,
                              void* d_out, int out_size)
{
    const float* X    = (const float*)d_in[0];
    const int*   gidx = (const int*)d_in[1];     // int32 (JAX x64 disabled)
    const float* W1   = (const float*)d_in[2];
    const float* b1   = (const float*)d_in[3];
    const float* W2   = (const float*)d_in[4];
    const float* b2   = (const float*)d_in[5];
    const float* W3   = (const float*)d_in[6];
    const float* b3   = (const float*)d_in[7];
    float* out = (float*)d_out;

    const int Nn = in_sizes[0] / 256;
    const int blocks = (Nn + 127) / 128;

    zero_out_kernel<<<(out_size + 255) / 256, 256>>>(out, out_size);
    setup_weights<<<(512 * 256 + 512 * 512 + 128 * 512 + 255) / 256, 256>>>(W1, W2, W3);

    const int smemA = 128 * XS_LD * 2 + 2 * T256E * 2;                       // 141,312
    const int smemB = 2 * STGE * 2 + 4 * T128E * 2 + 2 * T128E * 2 + 512;    // 221,696
    cudaFuncSetAttribute(gemm1_kernel,  cudaFuncAttributeMaxDynamicSharedMemorySize, smemA);
    cudaFuncSetAttribute(gemm23_kernel, cudaFuncAttributeMaxDynamicSharedMemorySize, smemB);

    gemm1_kernel<<<blocks, 256, smemA>>>(X, b1, Nn);
    gemm23_kernel<<<blocks, 256, smemB>>>(gidx, b2, b3, out, Nn);
}

// round 14
// speedup vs baseline: 1.0816x; 1.0816x over previous
#include <cuda_runtime.h>
#include <cuda_fp16.h>
#include <mma.h>
#include <math.h>
#include <cstdint>

using namespace nvcuda;

// ============================================================================
// Fully fused fp16 WMMA MLP + segment sum — ONE kernel, H1 SMEM-resident.
//   Phase 1: H1 = relu(X@W1+b1) -> H1s [128][520] fp16 (SMEM, never global)
//   Phase 2: per 128-col chunk mc: H2c = relu(H1s@W2+b2) -> Ps fp16,
//            Y += H2c @ W3c;  then g = silu(Y+b3), sorted segment-sum -> out.
// 512 threads, warp grid 4x4 (R12's winning occupancy config).
// SMEM region lifetimes (all aliasing behind drained cp.async + syncs):
//   H1s 133,120 | region 92,160: {X/W1 stages | W2 stages+Ps+W3s | fbuf} | gids
// ============================================================================

#define H1_LD  520              // 512 + 8 pad (fp16 elems)
#define WT_LD  72               // 64 + 8 pad
#define TLE    (128 * WT_LD)    // [128x64] tile elems (18,432 B)
#define FB_LD  132              // full fbuf fp32 ld
#define FB2_LD 68               // half-width fbuf fp32 ld

__device__ __align__(16) __half g_W1t[512 * 256];
__device__ __align__(16) __half g_W2t[512 * 512];
__device__ __align__(16) __half g_W3t[128 * 512];

__device__ __forceinline__ void cpa16(uint32_t dst, const void* src) {
    asm volatile("cp.async.cg.shared.global [%0], [%1], 16;" :: "r"(dst), "l"(src));
}
#define CPA_COMMIT() asm volatile("cp.async.commit_group;" ::: "memory")
#define CPA_WAIT0()  asm volatile("cp.async.wait_group 0;" ::: "memory")

// ---------------- setup: transpose weights to fp16 ----------------
__global__ void setup_weights(const float* __restrict__ W1, const float* __restrict__ W2,
                              const float* __restrict__ W3)
{
    int i = blockIdx.x * blockDim.x + threadIdx.x;
    if (i < 512 * 256) {                       // W1 [256K x 512N] -> [512][256]
        int n = i >> 8, k = i & 255;
        g_W1t[n * 256 + k] = __float2half_rn(W1[k * 512 + n]);
        return;
    }
    i -= 512 * 256;
    if (i < 512 * 512) {                       // W2 -> [512][512]
        int n = i >> 9, k = i & 511;
        g_W2t[n * 512 + k] = __float2half_rn(W2[k * 512 + n]);
        return;
    }
    i -= 512 * 512;
    if (i < 128 * 512) {                       // W3 [512K x 128N] -> [128][512]
        int n = i >> 9, k = i & 511;
        g_W3t[n * 512 + k] = __float2half_rn(W3[k * 128 + n]);
    }
}

__global__ void zero_out_kernel(float* out, int n)
{
    int i = blockIdx.x * blockDim.x + threadIdx.x;
    if (i < n) out[i] = 0.f;
}

// ============================================================================
// Fused kernel. 512 threads, 1 CTA per 128 node rows.
// ============================================================================
__global__ void __launch_bounds__(512, 1)
fused_mlp_kernel(const float* __restrict__ X, const int* __restrict__ gidx,
                 const float* __restrict__ b1, const float* __restrict__ b2,
                 const float* __restrict__ b3, float* __restrict__ out, int Nn)
{
    extern __shared__ char smem[];
    __half* H1s = (__half*)smem;                          // [128][520]  133,120 B
    __half* R   = H1s + 128 * H1_LD;                      // region      92,160 B
    int*    gids = (int*)((char*)R + 92160);              // 512 B
    // phase-1 layout in R:  Xst[2] @ elem 0 | W1st[2] @ elem 2*TLE
    // phase-2 layout in R:  W2st[2] @ elem 0 | Ps[2] @ 2*TLE | W3s @ 4*TLE
    __half* ST0 = R;                                      // stage base
    __half* Ps  = R + 2 * TLE;
    __half* W3s = R + 4 * TLE;
    float*  fbuf = (float*)R;                             // aliases stages (dead at use)
    const uint32_t ru = (uint32_t)__cvta_generic_to_shared(R);

    const int t   = threadIdx.x;
    const int wid = t >> 5;
    const int wm  = wid & 3;                              // 4 warps over M
    const int wn  = wid >> 2;                             // 4 warps over N
    const int row0 = blockIdx.x * 128;

    if (t < 128) gids[t] = (row0 + t < Nn) ? gidx[row0 + t] : -1;

    // ---------------- phase 1: H1s = relu(X @ W1 + b1) ----------------
    auto loadX = [&](int kt, int b) {                     // LDG fp32 -> cvt -> STS fp16
        __half* dst = ST0 + b * TLE;
        #pragma unroll
        for (int p = 0; p < 4; ++p) {
            int idx = t + p * 512;
            int r = idx >> 4, c4 = idx & 15;
            float4 v = (row0 + r < Nn)
                     ? *(const float4*)(X + (size_t)(row0 + r) * 256 + kt * 64 + c4 * 4)
                     : make_float4(0.f, 0.f, 0.f, 0.f);
            __half2* d = (__half2*)(dst + r * WT_LD + c4 * 4);
            d[0] = __floats2half2_rn(v.x, v.y);
            d[1] = __floats2half2_rn(v.z, v.w);
        }
    };
    auto prefW1 = [&](int nc, int kt, int b) {            // cp.async [128n][64k]
        const uint32_t base = ru + (uint32_t)(2 + b) * TLE * 2;
        #pragma unroll
        for (int p = 0; p < 2; ++p) {
            int idx = t + p * 512;
            int r = idx >> 3, c8 = idx & 7;
            cpa16(base + (uint32_t)(r * WT_LD + c8 * 8) * 2,
                  g_W1t + (size_t)(nc * 128 + r) * 256 + kt * 64 + c8 * 8);
        }
    };

    for (int nc = 0; nc < 4; ++nc) {
        wmma::fragment<wmma::accumulator, 16, 16, 16, float> acc[2][2];
        #pragma unroll
        for (int i = 0; i < 2; ++i)
            #pragma unroll
            for (int j = 0; j < 2; ++j) wmma::fill_fragment(acc[i][j], 0.f);

        loadX(0, 0); prefW1(nc, 0, 0); CPA_COMMIT();
        __syncthreads();                                  // X STS of buf0 visible
        for (int kt = 0; kt < 4; ++kt) {
            CPA_WAIT0();
            __syncthreads();                              // buf kt data ready; kt-1 compute done
            if (kt < 3) { loadX(kt + 1, (kt + 1) & 1); prefW1(nc, kt + 1, (kt + 1) & 1); CPA_COMMIT(); }
            const __half* Xb = ST0 + (kt & 1) * TLE;
            const __half* Wb = ST0 + (2 + (kt & 1)) * TLE;
            #pragma unroll
            for (int ks = 0; ks < 4; ++ks) {
                wmma::fragment<wmma::matrix_a, 16, 16, 16, __half, wmma::row_major> a[2];
                wmma::fragment<wmma::matrix_b, 16, 16, 16, __half, wmma::col_major> b[2];
                #pragma unroll
                for (int i = 0; i < 2; ++i)
                    wmma::load_matrix_sync(a[i], Xb + (wm * 32 + i * 16) * WT_LD + ks * 16, WT_LD);
                #pragma unroll
                for (int j = 0; j < 2; ++j)
                    wmma::load_matrix_sync(b[j], Wb + (wn * 32 + j * 16) * WT_LD + ks * 16, WT_LD);
                #pragma unroll
                for (int i = 0; i < 2; ++i)
                    #pragma unroll
                    for (int j = 0; j < 2; ++j)
                        wmma::mma_sync(acc[i][j], a[i], b[j], acc[i][j]);
            }
        }
        __syncthreads();                                  // compute done; stages dead -> fbuf

        // epilogue: all 16 warps store 128x128 chunk -> fbuf -> relu fp16 -> H1s
        #pragma unroll
        for (int i = 0; i < 2; ++i)
            #pragma unroll
            for (int j = 0; j < 2; ++j)
                wmma::store_matrix_sync(fbuf + (wm * 32 + i * 16) * FB_LD + wn * 32 + j * 16,
                                        acc[i][j], FB_LD, wmma::mem_row_major);
        __syncthreads();
        #pragma unroll 4
        for (int p = 0; p < 32; ++p) {
            int idx = t + p * 512;
            int r = idx >> 7, c = idx & 127;
            float v = fbuf[r * FB_LD + c] + b1[nc * 128 + c];
            v = v > 0.f ? v : 0.f;
            H1s[r * H1_LD + nc * 128 + c] = __float2half_rn(v);
        }
        __syncthreads();
    }

    // ------- phase 2: H2c = relu(H1s@W2+b2); Y += H2c @ W3c  (mc = 0..3) -------
    auto prefW2 = [&](int mc, int kt, int b) {            // cp.async [128n][64k]
        const uint32_t base = ru + (uint32_t)b * TLE * 2;
        #pragma unroll
        for (int p = 0; p < 2; ++p) {
            int idx = t + p * 512;
            int r = idx >> 3, c8 = idx & 7;
            cpa16(base + (uint32_t)(r * WT_LD + c8 * 8) * 2,
                  g_W2t + (size_t)(mc * 128 + r) * 512 + kt * 64 + c8 * 8);
        }
    };

    wmma::fragment<wmma::accumulator, 16, 16, 16, float> Y[2][2];
    #pragma unroll
    for (int i = 0; i < 2; ++i)
        #pragma unroll
        for (int j = 0; j < 2; ++j) wmma::fill_fragment(Y[i][j], 0.f);

    for (int mc = 0; mc < 4; ++mc) {
        wmma::fragment<wmma::accumulator, 16, 16, 16, float> acc2[2][2];
        #pragma unroll
        for (int i = 0; i < 2; ++i)
            #pragma unroll
            for (int j = 0; j < 2; ++j) wmma::fill_fragment(acc2[i][j], 0.f);

        // GEMM2: A straight from H1s (no staging), W2 cp.async 2-stage, kt=0..7
        prefW2(mc, 0, 0); CPA_COMMIT();
        for (int kt = 0; kt < 8; ++kt) {
            CPA_WAIT0();
            __syncthreads();
            if (kt < 7) { prefW2(mc, kt + 1, (kt + 1) & 1); CPA_COMMIT(); }
            const __half* Wb = ST0 + (kt & 1) * TLE;
            #pragma unroll
            for (int ks = 0; ks < 4; ++ks) {
                wmma::fragment<wmma::matrix_a, 16, 16, 16, __half, wmma::row_major> a[2];
                wmma::fragment<wmma::matrix_b, 16, 16, 16, __half, wmma::col_major> b[2];
                #pragma unroll
                for (int i = 0; i < 2; ++i)
                    wmma::load_matrix_sync(a[i], H1s + (wm * 32 + i * 16) * H1_LD + kt * 64 + ks * 16, H1_LD);
                #pragma unroll
                for (int j = 0; j < 2; ++j)
                    wmma::load_matrix_sync(b[j], Wb + (wn * 32 + j * 16) * WT_LD + ks * 16, WT_LD);
                #pragma unroll
                for (int i = 0; i < 2; ++i)
                    #pragma unroll
                    for (int j = 0; j < 2; ++j)
                        wmma::mma_sync(acc2[i][j], a[i], b[j], acc2[i][j]);
            }
        }
        __syncthreads();                                  // W2 stages dead -> fbuf68 alias safe

        // chunk epilogue: two 64-col passes through fbuf68 -> +b2, relu -> Ps
        #pragma unroll 1
        for (int h = 0; h < 2; ++h) {
            if ((wn >> 1) == h) {
                #pragma unroll
                for (int i = 0; i < 2; ++i)
                    #pragma unroll
                    for (int j = 0; j < 2; ++j)
                        wmma::store_matrix_sync(fbuf + (wm * 32 + i * 16) * FB2_LD + (wn & 1) * 32 + j * 16,
                                                acc2[i][j], FB2_LD, wmma::mem_row_major);
            }
            __syncthreads();
            #pragma unroll 4
            for (int p = 0; p < 16; ++p) {
                int idx = t + p * 512;
                int r = idx >> 6, c = idx & 63;
                float v = fbuf[r * FB2_LD + c] + b2[mc * 128 + h * 64 + c];
                v = v > 0.f ? v : 0.f;
                Ps[h * TLE + r * WT_LD + c] = __float2half_rn(v);
            }
            __syncthreads();
        }

        // GEMM3 partial: Y += Ps(128x128) @ W3t[:, mc*128..+128]
        #pragma unroll 1
        for (int kt3 = 0; kt3 < 2; ++kt3) {
            #pragma unroll
            for (int p = 0; p < 2; ++p) {                 // W3 tile [128n][64k] sync load
                int idx = t + p * 512;
                int r = idx >> 3, c8 = idx & 7;
                *(uint4*)&W3s[r * WT_LD + c8 * 8] =
                    *(const uint4*)(g_W3t + (size_t)r * 512 + mc * 128 + kt3 * 64 + c8 * 8);
            }
            __syncthreads();
            #pragma unroll
            for (int ks = 0; ks < 4; ++ks) {
                wmma::fragment<wmma::matrix_a, 16, 16, 16, __half, wmma::row_major> a[2];
                wmma::fragment<wmma::matrix_b, 16, 16, 16, __half, wmma::col_major> b[2];
                #pragma unroll
                for (int i = 0; i < 2; ++i)
                    wmma::load_matrix_sync(a[i], Ps + kt3 * TLE + (wm * 32 + i * 16) * WT_LD + ks * 16, WT_LD);
                #pragma unroll
                for (int j = 0; j < 2; ++j)
                    wmma::load_matrix_sync(b[j], W3s + (wn * 32 + j * 16) * WT_LD + ks * 16, WT_LD);
                #pragma unroll
                for (int i = 0; i < 2; ++i)
                    #pragma unroll
                    for (int j = 0; j < 2; ++j)
                        wmma::mma_sync(Y[i][j], a[i], b[j], Y[i][j]);
            }
            __syncthreads();
        }
    }

    // ---- final: Y -> fbuf, +b3, silu, sorted segment reduce, atomics ----
    #pragma unroll
    for (int i = 0; i < 2; ++i)
        #pragma unroll
        for (int j = 0; j < 2; ++j)
            wmma::store_matrix_sync(fbuf + (wm * 32 + i * 16) * FB_LD + wn * 32 + j * 16,
                                    Y[i][j], FB_LD, wmma::mem_row_major);
    __syncthreads();
    #pragma unroll 4
    for (int p = 0; p < 32; ++p) {
        int idx = t + p * 512;
        int r = idx >> 7, c = idx & 127;
        float y = fbuf[r * FB_LD + c] + b3[c];
        fbuf[r * FB_LD + c] = y / (1.f + expf(-y));
    }
    __syncthreads();

    if (t < 128) {
        int cur = gids[0];
        float s = 0.f;
        #pragma unroll 1
        for (int r = 0; r < 128; ++r) {
            int gi = gids[r];
            if (gi != cur) {
                if (cur >= 0) atomicAdd(&out[(size_t)cur * 128 + t], s);
                cur = gi; s = 0.f;
            }
            if (gi >= 0) s += fbuf[r * FB_LD + t];
        }
        if (cur >= 0) atomicAdd(&out[(size_t)cur * 128 + t], s);
    }
}

// ============================================================================
extern "C" void kernel_launch(void* const* d_in, const int* in_sizes, int n_in,
                              void* d_out, int out_size)
{
    const float* X    = (const float*)d_in[0];
    const int*   gidx = (const int*)d_in[1];     // int32 (JAX x64 disabled)
    const float* W1   = (const float*)d_in[2];
    const float* b1   = (const float*)d_in[3];
    const float* W2   = (const float*)d_in[4];
    const float* b2   = (const float*)d_in[5];
    const float* W3   = (const float*)d_in[6];
    const float* b3   = (const float*)d_in[7];
    float* out = (float*)d_out;

    const int Nn = in_sizes[0] / 256;
    const int blocks = (Nn + 127) / 128;

    zero_out_kernel<<<(out_size + 255) / 256, 256>>>(out, out_size);
    setup_weights<<<(512 * 256 + 512 * 512 + 128 * 512 + 255) / 256, 256>>>(W1, W2, W3);

    const int smemF = 128 * H1_LD * 2 + 92160 + 512;      // 225,792 B
    cudaFuncSetAttribute(fused_mlp_kernel, cudaFuncAttributeMaxDynamicSharedMemorySize, smemF);

    fused_mlp_kernel<<<blocks, 512, smemF>>>(X, gidx, b1, b2, b3, out, Nn);
}

// round 15
// speedup vs baseline: 1.1320x; 1.0466x over previous
#include <cuda_runtime.h>
#include <cuda_fp16.h>
#include <mma.h>
#include <math.h>
#include <cstdint>

using namespace nvcuda;

// ============================================================================
// Pure fp16 WMMA fused MLP + segment sum. 512 threads, warp tile 32x64,
// N-chunks of 256, cp.async SINGLE-SYNC pipelined mainloops, W3 double-
// buffered. (R12 champion + sync-reduction + W3 pipeline + merged setup.)
//   kernA: H1 = relu(X@W1+b1) -> g_H1 (fp16)
//   kernB: per 256-col chunk: H2c = relu(H1@W2+b2) -> Ps fp16,
//          Y += H2c @ W3c, then g = silu(Y+b3), sorted segment-sum -> out.
// ============================================================================

#define NODES_PAD (3907 * 128)
#define XS_LD  264             // 256 + 8 pad (fp16 elems)
#define WT_LD  72              // 64 + 8 pad
#define T128   (128 * WT_LD)   // [128x64] tile elems (18,432 B)
#define T256   (256 * WT_LD)   // [256x64] tile elems (36,864 B)
#define STG    (T128 + T256)   // kernel-B GEMM2 stage elems
#define FB_LD  132             // fbuf fp32 ld

__device__ __align__(16) __half g_W1t[512 * 256];
__device__ __align__(16) __half g_W2t[512 * 512];
__device__ __align__(16) __half g_W3t[128 * 512];
__device__ __align__(16) __half g_H1[(size_t)NODES_PAD * 512];

__device__ __forceinline__ void cpa16(uint32_t dst, const void* src) {
    asm volatile("cp.async.cg.shared.global [%0], [%1], 16;" :: "r"(dst), "l"(src));
}
#define CPA_COMMIT() asm volatile("cp.async.commit_group;" ::: "memory")
#define CPA_WAIT0()  asm volatile("cp.async.wait_group 0;" ::: "memory")

// -------- setup: transpose weights to fp16 + zero output (merged) --------
__global__ void setup_weights(const float* __restrict__ W1, const float* __restrict__ W2,
                              const float* __restrict__ W3, float* __restrict__ out,
                              int out_n)
{
    int i = blockIdx.x * blockDim.x + threadIdx.x;
    if (i < 512 * 256) {
        int n = i >> 8, k = i & 255;
        g_W1t[n * 256 + k] = __float2half_rn(W1[k * 512 + n]);
        return;
    }
    i -= 512 * 256;
    if (i < 512 * 512) {
        int n = i >> 9, k = i & 511;
        g_W2t[n * 512 + k] = __float2half_rn(W2[k * 512 + n]);
        return;
    }
    i -= 512 * 512;
    if (i < 128 * 512) {
        int n = i >> 9, k = i & 511;
        g_W3t[n * 512 + k] = __float2half_rn(W3[k * 128 + n]);
        return;
    }
    i -= 128 * 512;
    if (i < out_n) out[i] = 0.f;
}

// ============================================================================
// Kernel A: H1 = relu(X @ W1 + b1).  512 threads, 2 N-chunks of 256.
// SMEM: Xs [128][264] resident | SW 2 stages x [256][72]  (fbuf aliases SW)
// ============================================================================
__global__ void __launch_bounds__(512, 1)
gemm1_kernel(const float* __restrict__ X, const float* __restrict__ b1, int Nn)
{
    extern __shared__ char smem[];
    __half* Xs = (__half*)smem;                       // 67,584 B
    __half* SW = Xs + 128 * XS_LD;                    // 2 x 36,864 B
    float*  fbuf = (float*)SW;                        // alias (stages dead at use)
    const uint32_t swu = (uint32_t)__cvta_generic_to_shared(SW);

    const int t   = threadIdx.x;
    const int wid = t >> 5;
    const int wm  = wid & 3;          // 4 warps over M (32 rows each)
    const int wn  = wid >> 2;         // 4 warps over N (64 cols each)
    const int row0 = blockIdx.x * 128;

    // ---- load X (128 x 256 fp32) -> fp16 ----
    #pragma unroll 4
    for (int p = 0; p < 16; ++p) {
        int idx = t + p * 512;
        int r = idx >> 6, c4 = idx & 63;
        float4 v = (row0 + r < Nn) ? *(const float4*)(X + (size_t)(row0 + r) * 256 + c4 * 4)
                                   : make_float4(0.f, 0.f, 0.f, 0.f);
        Xs[r * XS_LD + c4 * 4 + 0] = __float2half_rn(v.x);
        Xs[r * XS_LD + c4 * 4 + 1] = __float2half_rn(v.y);
        Xs[r * XS_LD + c4 * 4 + 2] = __float2half_rn(v.z);
        Xs[r * XS_LD + c4 * 4 + 3] = __float2half_rn(v.w);
    }
    __syncthreads();

    auto prefW = [&](int nc, int kt, int b) {         // W1t tile [256n][64k]
        const uint32_t base = swu + (uint32_t)b * T256 * 2;
        #pragma unroll
        for (int p = 0; p < 4; ++p) {
            int idx = t + p * 512;
            int r = idx >> 3, c8 = idx & 7;
            cpa16(base + (uint32_t)(r * WT_LD + c8 * 8) * 2,
                  g_W1t + (size_t)(nc * 256 + r) * 256 + kt * 64 + c8 * 8);
        }
    };

    for (int nc = 0; nc < 2; ++nc) {
        wmma::fragment<wmma::accumulator, 16, 16, 16, float> acc[2][4];
        #pragma unroll
        for (int i = 0; i < 2; ++i)
            #pragma unroll
            for (int j = 0; j < 4; ++j) wmma::fill_fragment(acc[i][j], 0.f);

        prefW(nc, 0, 0); CPA_COMMIT();
        for (int kt = 0; kt < 4; ++kt) {              // single-sync pipelined
            CPA_WAIT0();
            __syncthreads();                          // data kt ready; kt-1 compute done
            if (kt < 3) { prefW(nc, kt + 1, (kt + 1) & 1); CPA_COMMIT(); }
            const __half* Wb = SW + (kt & 1) * T256;
            #pragma unroll
            for (int ks = 0; ks < 4; ++ks) {
                wmma::fragment<wmma::matrix_a, 16, 16, 16, __half, wmma::row_major> a[2];
                wmma::fragment<wmma::matrix_b, 16, 16, 16, __half, wmma::col_major> b[4];
                #pragma unroll
                for (int i = 0; i < 2; ++i)
                    wmma::load_matrix_sync(a[i], Xs + (wm * 32 + i * 16) * XS_LD + kt * 64 + ks * 16, XS_LD);
                #pragma unroll
                for (int j = 0; j < 4; ++j)
                    wmma::load_matrix_sync(b[j], Wb + (wn * 64 + j * 16) * WT_LD + ks * 16, WT_LD);
                #pragma unroll
                for (int i = 0; i < 2; ++i)
                    #pragma unroll
                    for (int j = 0; j < 4; ++j)
                        wmma::mma_sync(acc[i][j], a[i], b[j], acc[i][j]);
            }
        }
        __syncthreads();                              // all compute done before fbuf alias

        // ---- epilogue: two 128-col passes through fbuf (aliases SW) ----
        #pragma unroll 1
        for (int h = 0; h < 2; ++h) {
            if ((wn >> 1) == h) {
                #pragma unroll
                for (int i = 0; i < 2; ++i)
                    #pragma unroll
                    for (int j = 0; j < 4; ++j)
                        wmma::store_matrix_sync(fbuf + (wm * 32 + i * 16) * FB_LD + (wn & 1) * 64 + j * 16,
                                                acc[i][j], FB_LD, wmma::mem_row_major);
            }
            __syncthreads();
            int col0 = nc * 256 + h * 128;
            #pragma unroll 4
            for (int p = 0; p < 32; ++p) {
                int idx = t + p * 512;
                int r = idx >> 7, c = idx & 127;
                if (row0 + r < Nn) {
                    float v = fbuf[r * FB_LD + c] + b1[col0 + c];
                    v = v > 0.f ? v : 0.f;
                    g_H1[(size_t)(row0 + r) * 512 + col0 + c] = __float2half_rn(v);
                }
            }
            __syncthreads();
        }
    }
}

// ============================================================================
// Kernel B: 2 N-chunks of 256. 512 threads.
// SMEM: SG 2 stages x (Hs [128][72] + W2s [256][72]) | Ps 4 x [128][72] |
//       W3s 2 x [128][72] | gids.  fbuf [128][132] f32 aliases SG.
// Total: 110,592 + 73,728 + 36,864 + 512 = 221,696 B.
// ============================================================================
__global__ void __launch_bounds__(512, 1)
gemm23_kernel(const int* __restrict__ gidx,
              const float* __restrict__ b2, const float* __restrict__ b3,
              float* __restrict__ out, int Nn)
{
    extern __shared__ char smem[];
    __half* SG  = (__half*)smem;                 // 2 x STG
    __half* Ps  = SG + 2 * STG;                  // 4 k-subtiles [128][72]
    __half* W3s = Ps + 4 * T128;                 // 2 bufs [128][72]
    int*    gids = (int*)(W3s + 2 * T128);
    float*  fbuf = (float*)SG;                   // alias (stages dead at use)
    const uint32_t sgu = (uint32_t)__cvta_generic_to_shared(SG);
    const uint32_t w3u = (uint32_t)__cvta_generic_to_shared(W3s);

    const int t   = threadIdx.x;
    const int wid = t >> 5;
    const int wm  = wid & 3;
    const int wn  = wid >> 2;                    // 0..3
    const int row0 = blockIdx.x * 128;

    if (t < 128) gids[t] = (row0 + t < Nn) ? gidx[row0 + t] : -1;

    auto prefG2 = [&](int mc, int kt, int b) {
        const uint32_t base = sgu + (uint32_t)b * STG * 2;
        #pragma unroll
        for (int p = 0; p < 2; ++p) {            // Hs [128][64]
            int idx = t + p * 512;
            int r = idx >> 3, c8 = idx & 7;
            cpa16(base + (uint32_t)(r * WT_LD + c8 * 8) * 2,
                  g_H1 + (size_t)(row0 + r) * 512 + kt * 64 + c8 * 8);
        }
        #pragma unroll
        for (int p = 0; p < 4; ++p) {            // W2s [256][64]
            int idx = t + p * 512;
            int r = idx >> 3, c8 = idx & 7;
            cpa16(base + (uint32_t)T128 * 2 + (uint32_t)(r * WT_LD + c8 * 8) * 2,
                  g_W2t + (size_t)(mc * 256 + r) * 512 + kt * 64 + c8 * 8);
        }
    };
    auto prefW3 = [&](int mc, int kt3, int b) {  // W3t tile [128n][64k]
        const uint32_t base = w3u + (uint32_t)b * T128 * 2;
        #pragma unroll
        for (int p = 0; p < 2; ++p) {
            int idx = t + p * 512;
            int r = idx >> 3, c8 = idx & 7;
            cpa16(base + (uint32_t)(r * WT_LD + c8 * 8) * 2,
                  g_W3t + (size_t)r * 512 + mc * 256 + kt3 * 64 + c8 * 8);
        }
    };

    wmma::fragment<wmma::accumulator, 16, 16, 16, float> Y[2][2];
    #pragma unroll
    for (int i = 0; i < 2; ++i)
        #pragma unroll
        for (int j = 0; j < 2; ++j) wmma::fill_fragment(Y[i][j], 0.f);

    for (int mc = 0; mc < 2; ++mc) {
        wmma::fragment<wmma::accumulator, 16, 16, 16, float> acc2[2][4];
        #pragma unroll
        for (int i = 0; i < 2; ++i)
            #pragma unroll
            for (int j = 0; j < 4; ++j) wmma::fill_fragment(acc2[i][j], 0.f);

        // ---- GEMM2 chunk, single-sync pipelined, kt = 0..7 ----
        prefG2(mc, 0, 0); CPA_COMMIT();
        for (int kt = 0; kt < 8; ++kt) {
            CPA_WAIT0();
            __syncthreads();                      // data kt ready; kt-1 compute done
            if (kt < 7) { prefG2(mc, kt + 1, (kt + 1) & 1); CPA_COMMIT(); }
            const __half* Hs  = SG + (kt & 1) * STG;
            const __half* W2s = Hs + T128;
            #pragma unroll
            for (int ks = 0; ks < 4; ++ks) {
                wmma::fragment<wmma::matrix_a, 16, 16, 16, __half, wmma::row_major> a[2];
                wmma::fragment<wmma::matrix_b, 16, 16, 16, __half, wmma::col_major> b[4];
                #pragma unroll
                for (int i = 0; i < 2; ++i)
                    wmma::load_matrix_sync(a[i], Hs + (wm * 32 + i * 16) * WT_LD + ks * 16, WT_LD);
                #pragma unroll
                for (int j = 0; j < 4; ++j)
                    wmma::load_matrix_sync(b[j], W2s + (wn * 64 + j * 16) * WT_LD + ks * 16, WT_LD);
                #pragma unroll
                for (int i = 0; i < 2; ++i)
                    #pragma unroll
                    for (int j = 0; j < 4; ++j)
                        wmma::mma_sync(acc2[i][j], a[i], b[j], acc2[i][j]);
            }
        }
        prefW3(mc, 0, 0); CPA_COMMIT();           // overlaps chunk epilogue
        __syncthreads();                          // compute done before fbuf (aliases SG)

        // ---- chunk epilogue: two 128-col passes -> Ps (fp16) ----
        #pragma unroll 1
        for (int h = 0; h < 2; ++h) {
            if ((wn >> 1) == h) {
                #pragma unroll
                for (int i = 0; i < 2; ++i)
                    #pragma unroll
                    for (int j = 0; j < 4; ++j)
                        wmma::store_matrix_sync(fbuf + (wm * 32 + i * 16) * FB_LD + (wn & 1) * 64 + j * 16,
                                                acc2[i][j], FB_LD, wmma::mem_row_major);
            }
            __syncthreads();
            #pragma unroll 4
            for (int p = 0; p < 32; ++p) {
                int idx = t + p * 512;
                int r = idx >> 7, c = idx & 127;
                float v = fbuf[r * FB_LD + c] + b2[mc * 256 + h * 128 + c];
                v = v > 0.f ? v : 0.f;
                int sub = h * 2 + (c >> 6);
                Ps[sub * T128 + r * WT_LD + (c & 63)] = __float2half_rn(v);
            }
            __syncthreads();
        }

        // ---- GEMM3 partial: Y += Ps (128x256) @ W3t[:, mc*256..+256] ----
        for (int kt3 = 0; kt3 < 4; ++kt3) {       // single-sync pipelined
            CPA_WAIT0();
            __syncthreads();
            if (kt3 < 3) { prefW3(mc, kt3 + 1, (kt3 + 1) & 1); CPA_COMMIT(); }
            const __half* Wb = W3s + (kt3 & 1) * T128;
            const __half* Pb = Ps + kt3 * T128;
            #pragma unroll
            for (int ks = 0; ks < 4; ++ks) {
                wmma::fragment<wmma::matrix_a, 16, 16, 16, __half, wmma::row_major> a[2];
                wmma::fragment<wmma::matrix_b, 16, 16, 16, __half, wmma::col_major> b[2];
                #pragma unroll
                for (int i = 0; i < 2; ++i)
                    wmma::load_matrix_sync(a[i], Pb + (wm * 32 + i * 16) * WT_LD + ks * 16, WT_LD);
                #pragma unroll
                for (int j = 0; j < 2; ++j)
                    wmma::load_matrix_sync(b[j], Wb + (wn * 32 + j * 16) * WT_LD + ks * 16, WT_LD);
                #pragma unroll
                for (int i = 0; i < 2; ++i)
                    #pragma unroll
                    for (int j = 0; j < 2; ++j)
                        wmma::mma_sync(Y[i][j], a[i], b[j], Y[i][j]);
            }
        }
        __syncthreads();                          // GEMM3 done before Ps/SG reuse next mc
    }

    // ---- final: Y -> fbuf, +b3, silu, sorted segment reduce, atomics ----
    #pragma unroll
    for (int i = 0; i < 2; ++i)
        #pragma unroll
        for (int j = 0; j < 2; ++j)
            wmma::store_matrix_sync(fbuf + (wm * 32 + i * 16) * FB_LD + wn * 32 + j * 16,
                                    Y[i][j], FB_LD, wmma::mem_row_major);
    __syncthreads();
    #pragma unroll 4
    for (int p = 0; p < 32; ++p) {
        int idx = t + p * 512;
        int r = idx >> 7, c = idx & 127;
        float y = fbuf[r * FB_LD + c] + b3[c];
        fbuf[r * FB_LD + c] = y / (1.f + expf(-y));
    }
    __syncthreads();

    if (t < 128) {
        int cur = gids[0];
        float s = 0.f;
        #pragma unroll 1
        for (int r = 0; r < 128; ++r) {
            int gi = gids[r];
            if (gi != cur) {
                if (cur >= 0) atomicAdd(&out[(size_t)cur * 128 + t], s);
                cur = gi; s = 0.f;
            }
            if (gi >= 0) s += fbuf[r * FB_LD + t];
        }
        if (cur >= 0) atomicAdd(&out[(size_t)cur * 128 + t], s);
    }
}

// ============================================================================
extern "C" void kernel_launch(void* const* d_in, const int* in_sizes, int n_in,
                              void* d_out, int out_size)
{
    const float* X    = (const float*)d_in[0];
    const int*   gidx = (const int*)d_in[1];     // int32 (JAX x64 disabled)
    const float* W1   = (const float*)d_in[2];
    const float* b1   = (const float*)d_in[3];
    const float* W2   = (const float*)d_in[4];
    const float* b2   = (const float*)d_in[5];
    const float* W3   = (const float*)d_in[6];
    const float* b3   = (const float*)d_in[7];
    float* out = (float*)d_out;

    const int Nn = in_sizes[0] / 256;
    const int blocks = (Nn + 127) / 128;

    const int setup_work = 512 * 256 + 512 * 512 + 128 * 512 + out_size;
    setup_weights<<<(setup_work + 255) / 256, 256>>>(W1, W2, W3, out, out_size);

    const int smemA = 128 * XS_LD * 2 + 2 * T256 * 2;                    // 141,312
    const int smemB = 2 * STG * 2 + 4 * T128 * 2 + 2 * T128 * 2 + 512;   // 221,696
    cudaFuncSetAttribute(gemm1_kernel,  cudaFuncAttributeMaxDynamicSharedMemorySize, smemA);
    cudaFuncSetAttribute(gemm23_kernel, cudaFuncAttributeMaxDynamicSharedMemorySize, smemB);

    gemm1_kernel<<<blocks, 512, smemA>>>(X, b1, Nn);
    gemm23_kernel<<<blocks, 512, smemB>>>(gidx, b2, b3, out, Nn);
}

// round 16
// speedup vs baseline: 1.1855x; 1.0472x over previous
#include <cuda_runtime.h>
#include <cuda_fp16.h>
#include <mma.h>
#include <math.h>
#include <cstdint>

using namespace nvcuda;

// ============================================================================
// Pure fp16 WMMA fused MLP + segment sum. 512 threads, warp tile 32x64,
// N-chunks of 256, cp.async single-sync pipelined mainloops, W3 double-
// buffered. R16: next-mc GEMM2 prefetch under GEMM3, kernel-A W1 prefetch
// before X load, 4-way parallel segment reduce.
//   kernA: H1 = relu(X@W1+b1) -> g_H1 (fp16)
//   kernB: per 256-col chunk: H2c = relu(H1@W2+b2) -> Ps fp16,
//          Y += H2c @ W3c, then g = silu(Y+b3), sorted segment-sum -> out.
// ============================================================================

#define NODES_PAD (3907 * 128)
#define XS_LD  264             // 256 + 8 pad (fp16 elems)
#define WT_LD  72              // 64 + 8 pad
#define T128   (128 * WT_LD)   // [128x64] tile elems (18,432 B)
#define T256   (256 * WT_LD)   // [256x64] tile elems (36,864 B)
#define STG    (T128 + T256)   // kernel-B GEMM2 stage elems
#define FB_LD  132             // fbuf fp32 ld

__device__ __align__(16) __half g_W1t[512 * 256];
__device__ __align__(16) __half g_W2t[512 * 512];
__device__ __align__(16) __half g_W3t[128 * 512];
__device__ __align__(16) __half g_H1[(size_t)NODES_PAD * 512];

__device__ __forceinline__ void cpa16(uint32_t dst, const void* src) {
    asm volatile("cp.async.cg.shared.global [%0], [%1], 16;" :: "r"(dst), "l"(src));
}
#define CPA_COMMIT() asm volatile("cp.async.commit_group;" ::: "memory")
#define CPA_WAIT0()  asm volatile("cp.async.wait_group 0;" ::: "memory")

// -------- setup: transpose weights to fp16 + zero output (merged) --------
__global__ void setup_weights(const float* __restrict__ W1, const float* __restrict__ W2,
                              const float* __restrict__ W3, float* __restrict__ out,
                              int out_n)
{
    int i = blockIdx.x * blockDim.x + threadIdx.x;
    if (i < 512 * 256) {
        int n = i >> 8, k = i & 255;
        g_W1t[n * 256 + k] = __float2half_rn(W1[k * 512 + n]);
        return;
    }
    i -= 512 * 256;
    if (i < 512 * 512) {
        int n = i >> 9, k = i & 511;
        g_W2t[n * 512 + k] = __float2half_rn(W2[k * 512 + n]);
        return;
    }
    i -= 512 * 512;
    if (i < 128 * 512) {
        int n = i >> 9, k = i & 511;
        g_W3t[n * 512 + k] = __float2half_rn(W3[k * 128 + n]);
        return;
    }
    i -= 128 * 512;
    if (i < out_n) out[i] = 0.f;
}

// ============================================================================
// Kernel A: H1 = relu(X @ W1 + b1).  512 threads, 2 N-chunks of 256.
// SMEM: Xs [128][264] resident | SW 2 stages x [256][72]  (fbuf aliases SW)
// ============================================================================
__global__ void __launch_bounds__(512, 1)
gemm1_kernel(const float* __restrict__ X, const float* __restrict__ b1, int Nn)
{
    extern __shared__ char smem[];
    __half* Xs = (__half*)smem;                       // 67,584 B
    __half* SW = Xs + 128 * XS_LD;                    // 2 x 36,864 B
    float*  fbuf = (float*)SW;                        // alias (stages dead at use)
    const uint32_t swu = (uint32_t)__cvta_generic_to_shared(SW);

    const int t   = threadIdx.x;
    const int wid = t >> 5;
    const int wm  = wid & 3;          // 4 warps over M (32 rows each)
    const int wn  = wid >> 2;         // 4 warps over N (64 cols each)
    const int row0 = blockIdx.x * 128;

    auto prefW = [&](int nc, int kt, int b) {         // W1t tile [256n][64k]
        const uint32_t base = swu + (uint32_t)b * T256 * 2;
        #pragma unroll
        for (int p = 0; p < 4; ++p) {
            int idx = t + p * 512;
            int r = idx >> 3, c8 = idx & 7;
            cpa16(base + (uint32_t)(r * WT_LD + c8 * 8) * 2,
                  g_W1t + (size_t)(nc * 256 + r) * 256 + kt * 64 + c8 * 8);
        }
    };

    // first W1 tile in flight while X loads/converts
    prefW(0, 0, 0); CPA_COMMIT();

    // ---- load X (128 x 256 fp32) -> fp16 ----
    #pragma unroll 4
    for (int p = 0; p < 16; ++p) {
        int idx = t + p * 512;
        int r = idx >> 6, c4 = idx & 63;
        float4 v = (row0 + r < Nn) ? *(const float4*)(X + (size_t)(row0 + r) * 256 + c4 * 4)
                                   : make_float4(0.f, 0.f, 0.f, 0.f);
        Xs[r * XS_LD + c4 * 4 + 0] = __float2half_rn(v.x);
        Xs[r * XS_LD + c4 * 4 + 1] = __float2half_rn(v.y);
        Xs[r * XS_LD + c4 * 4 + 2] = __float2half_rn(v.z);
        Xs[r * XS_LD + c4 * 4 + 3] = __float2half_rn(v.w);
    }
    __syncthreads();

    for (int nc = 0; nc < 2; ++nc) {
        wmma::fragment<wmma::accumulator, 16, 16, 16, float> acc[2][4];
        #pragma unroll
        for (int i = 0; i < 2; ++i)
            #pragma unroll
            for (int j = 0; j < 4; ++j) wmma::fill_fragment(acc[i][j], 0.f);

        if (nc > 0) { prefW(nc, 0, 0); CPA_COMMIT(); }
        for (int kt = 0; kt < 4; ++kt) {              // single-sync pipelined
            CPA_WAIT0();
            __syncthreads();                          // data kt ready; kt-1 compute done
            if (kt < 3) { prefW(nc, kt + 1, (kt + 1) & 1); CPA_COMMIT(); }
            const __half* Wb = SW + (kt & 1) * T256;
            #pragma unroll
            for (int ks = 0; ks < 4; ++ks) {
                wmma::fragment<wmma::matrix_a, 16, 16, 16, __half, wmma::row_major> a[2];
                wmma::fragment<wmma::matrix_b, 16, 16, 16, __half, wmma::col_major> b[4];
                #pragma unroll
                for (int i = 0; i < 2; ++i)
                    wmma::load_matrix_sync(a[i], Xs + (wm * 32 + i * 16) * XS_LD + kt * 64 + ks * 16, XS_LD);
                #pragma unroll
                for (int j = 0; j < 4; ++j)
                    wmma::load_matrix_sync(b[j], Wb + (wn * 64 + j * 16) * WT_LD + ks * 16, WT_LD);
                #pragma unroll
                for (int i = 0; i < 2; ++i)
                    #pragma unroll
                    for (int j = 0; j < 4; ++j)
                        wmma::mma_sync(acc[i][j], a[i], b[j], acc[i][j]);
            }
        }
        __syncthreads();                              // all compute done before fbuf alias

        // ---- epilogue: two 128-col passes through fbuf (aliases SW) ----
        #pragma unroll 1
        for (int h = 0; h < 2; ++h) {
            if ((wn >> 1) == h) {
                #pragma unroll
                for (int i = 0; i < 2; ++i)
                    #pragma unroll
                    for (int j = 0; j < 4; ++j)
                        wmma::store_matrix_sync(fbuf + (wm * 32 + i * 16) * FB_LD + (wn & 1) * 64 + j * 16,
                                                acc[i][j], FB_LD, wmma::mem_row_major);
            }
            __syncthreads();
            int col0 = nc * 256 + h * 128;
            #pragma unroll 4
            for (int p = 0; p < 32; ++p) {
                int idx = t + p * 512;
                int r = idx >> 7, c = idx & 127;
                if (row0 + r < Nn) {
                    float v = fbuf[r * FB_LD + c] + b1[col0 + c];
                    v = v > 0.f ? v : 0.f;
                    g_H1[(size_t)(row0 + r) * 512 + col0 + c] = __float2half_rn(v);
                }
            }
            __syncthreads();
        }
    }
}

// ============================================================================
// Kernel B: 2 N-chunks of 256. 512 threads.
// SMEM: SG 2 stages x (Hs [128][72] + W2s [256][72]) | Ps 4 x [128][72] |
//       W3s 2 x [128][72] | gids.  fbuf [128][132] f32 aliases SG.
// ============================================================================
__global__ void __launch_bounds__(512, 1)
gemm23_kernel(const int* __restrict__ gidx,
              const float* __restrict__ b2, const float* __restrict__ b3,
              float* __restrict__ out, int Nn)
{
    extern __shared__ char smem[];
    __half* SG  = (__half*)smem;                 // 2 x STG
    __half* Ps  = SG + 2 * STG;                  // 4 k-subtiles [128][72]
    __half* W3s = Ps + 4 * T128;                 // 2 bufs [128][72]
    int*    gids = (int*)(W3s + 2 * T128);
    float*  fbuf = (float*)SG;                   // alias (stages dead at use)
    const uint32_t sgu = (uint32_t)__cvta_generic_to_shared(SG);
    const uint32_t w3u = (uint32_t)__cvta_generic_to_shared(W3s);

    const int t   = threadIdx.x;
    const int wid = t >> 5;
    const int wm  = wid & 3;
    const int wn  = wid >> 2;                    // 0..3
    const int row0 = blockIdx.x * 128;

    if (t < 128) gids[t] = (row0 + t < Nn) ? gidx[row0 + t] : -1;

    auto prefG2 = [&](int mc, int kt, int b) {
        const uint32_t base = sgu + (uint32_t)b * STG * 2;
        #pragma unroll
        for (int p = 0; p < 2; ++p) {            // Hs [128][64]
            int idx = t + p * 512;
            int r = idx >> 3, c8 = idx & 7;
            cpa16(base + (uint32_t)(r * WT_LD + c8 * 8) * 2,
                  g_H1 + (size_t)(row0 + r) * 512 + kt * 64 + c8 * 8);
        }
        #pragma unroll
        for (int p = 0; p < 4; ++p) {            // W2s [256][64]
            int idx = t + p * 512;
            int r = idx >> 3, c8 = idx & 7;
            cpa16(base + (uint32_t)T128 * 2 + (uint32_t)(r * WT_LD + c8 * 8) * 2,
                  g_W2t + (size_t)(mc * 256 + r) * 512 + kt * 64 + c8 * 8);
        }
    };
    auto prefW3 = [&](int mc, int kt3, int b) {  // W3t tile [128n][64k]
        const uint32_t base = w3u + (uint32_t)b * T128 * 2;
        #pragma unroll
        for (int p = 0; p < 2; ++p) {
            int idx = t + p * 512;
            int r = idx >> 3, c8 = idx & 7;
            cpa16(base + (uint32_t)(r * WT_LD + c8 * 8) * 2,
                  g_W3t + (size_t)r * 512 + mc * 256 + kt3 * 64 + c8 * 8);
        }
    };

    wmma::fragment<wmma::accumulator, 16, 16, 16, float> Y[2][2];
    #pragma unroll
    for (int i = 0; i < 2; ++i)
        #pragma unroll
        for (int j = 0; j < 2; ++j) wmma::fill_fragment(Y[i][j], 0.f);

    prefG2(0, 0, 0); CPA_COMMIT();               // initial (mc=0) prefetch

    for (int mc = 0; mc < 2; ++mc) {
        wmma::fragment<wmma::accumulator, 16, 16, 16, float> acc2[2][4];
        #pragma unroll
        for (int i = 0; i < 2; ++i)
            #pragma unroll
            for (int j = 0; j < 4; ++j) wmma::fill_fragment(acc2[i][j], 0.f);

        // ---- GEMM2 chunk, single-sync pipelined, kt = 0..7 ----
        // (mc>0: buf0 tile was prefetched during previous mc's GEMM3)
        for (int kt = 0; kt < 8; ++kt) {
            CPA_WAIT0();
            __syncthreads();                      // data kt ready; kt-1 compute done
            if (kt < 7) { prefG2(mc, kt + 1, (kt + 1) & 1); CPA_COMMIT(); }
            const __half* Hs  = SG + (kt & 1) * STG;
            const __half* W2s = Hs + T128;
            #pragma unroll
            for (int ks = 0; ks < 4; ++ks) {
                wmma::fragment<wmma::matrix_a, 16, 16, 16, __half, wmma::row_major> a[2];
                wmma::fragment<wmma::matrix_b, 16, 16, 16, __half, wmma::col_major> b[4];
                #pragma unroll
                for (int i = 0; i < 2; ++i)
                    wmma::load_matrix_sync(a[i], Hs + (wm * 32 + i * 16) * WT_LD + ks * 16, WT_LD);
                #pragma unroll
                for (int j = 0; j < 4; ++j)
                    wmma::load_matrix_sync(b[j], W2s + (wn * 64 + j * 16) * WT_LD + ks * 16, WT_LD);
                #pragma unroll
                for (int i = 0; i < 2; ++i)
                    #pragma unroll
                    for (int j = 0; j < 4; ++j)
                        wmma::mma_sync(acc2[i][j], a[i], b[j], acc2[i][j]);
            }
        }
        prefW3(mc, 0, 0); CPA_COMMIT();           // overlaps chunk epilogue
        __syncthreads();                          // compute done before fbuf (aliases SG)

        // ---- chunk epilogue: two 128-col passes -> Ps (fp16) ----
        #pragma unroll 1
        for (int h = 0; h < 2; ++h) {
            if ((wn >> 1) == h) {
                #pragma unroll
                for (int i = 0; i < 2; ++i)
                    #pragma unroll
                    for (int j = 0; j < 4; ++j)
                        wmma::store_matrix_sync(fbuf + (wm * 32 + i * 16) * FB_LD + (wn & 1) * 64 + j * 16,
                                                acc2[i][j], FB_LD, wmma::mem_row_major);
            }
            __syncthreads();
            #pragma unroll 4
            for (int p = 0; p < 32; ++p) {
                int idx = t + p * 512;
                int r = idx >> 7, c = idx & 127;
                float v = fbuf[r * FB_LD + c] + b2[mc * 256 + h * 128 + c];
                v = v > 0.f ? v : 0.f;
                int sub = h * 2 + (c >> 6);
                Ps[sub * T128 + r * WT_LD + (c & 63)] = __float2half_rn(v);
            }
            __syncthreads();
        }

        // next-mc GEMM2 tiles prefetched under GEMM3 (SG/fbuf now dead)
        if (mc < 1) { prefG2(mc + 1, 0, 0); CPA_COMMIT(); }

        // ---- GEMM3 partial: Y += Ps (128x256) @ W3t[:, mc*256..+256] ----
        for (int kt3 = 0; kt3 < 4; ++kt3) {       // single-sync pipelined
            CPA_WAIT0();
            __syncthreads();
            if (kt3 < 3) { prefW3(mc, kt3 + 1, (kt3 + 1) & 1); CPA_COMMIT(); }
            const __half* Wb = W3s + (kt3 & 1) * T128;
            const __half* Pb = Ps + kt3 * T128;
            #pragma unroll
            for (int ks = 0; ks < 4; ++ks) {
                wmma::fragment<wmma::matrix_a, 16, 16, 16, __half, wmma::row_major> a[2];
                wmma::fragment<wmma::matrix_b, 16, 16, 16, __half, wmma::col_major> b[2];
                #pragma unroll
                for (int i = 0; i < 2; ++i)
                    wmma::load_matrix_sync(a[i], Pb + (wm * 32 + i * 16) * WT_LD + ks * 16, WT_LD);
                #pragma unroll
                for (int j = 0; j < 2; ++j)
                    wmma::load_matrix_sync(b[j], Wb + (wn * 32 + j * 16) * WT_LD + ks * 16, WT_LD);
                #pragma unroll
                for (int i = 0; i < 2; ++i)
                    #pragma unroll
                    for (int j = 0; j < 2; ++j)
                        wmma::mma_sync(Y[i][j], a[i], b[j], Y[i][j]);
            }
        }
        __syncthreads();                          // GEMM3 done before Ps reuse next mc
    }

    // ---- final: Y -> fbuf, +b3, silu, 4-strip parallel segment reduce ----
    #pragma unroll
    for (int i = 0; i < 2; ++i)
        #pragma unroll
        for (int j = 0; j < 2; ++j)
            wmma::store_matrix_sync(fbuf + (wm * 32 + i * 16) * FB_LD + wn * 32 + j * 16,
                                    Y[i][j], FB_LD, wmma::mem_row_major);
    __syncthreads();
    #pragma unroll 4
    for (int p = 0; p < 32; ++p) {
        int idx = t + p * 512;
        int r = idx >> 7, c = idx & 127;
        float y = fbuf[r * FB_LD + c] + b3[c];
        fbuf[r * FB_LD + c] = y / (1.f + expf(-y));
    }
    __syncthreads();

    {
        const int s = t >> 7, c = t & 127;        // 4 row-strips x 128 cols
        const int rbeg = s * 32, rend = rbeg + 32;
        int cur = gids[rbeg];
        float sum = 0.f;
        #pragma unroll 1
        for (int r = rbeg; r < rend; ++r) {
            int gi = gids[r];
            if (gi != cur) {
                if (cur >= 0) atomicAdd(&out[(size_t)cur * 128 + c], sum);
                cur = gi; sum = 0.f;
            }
            if (gi >= 0) sum += fbuf[r * FB_LD + c];
        }
        if (cur >= 0) atomicAdd(&out[(size_t)cur * 128 + c], sum);
    }
}

// ============================================================================
extern "C" void kernel_launch(void* const* d_in, const int* in_sizes, int n_in,
                              void* d_out, int out_size)
{
    const float* X    = (const float*)d_in[0];
    const int*   gidx = (const int*)d_in[1];     // int32 (JAX x64 disabled)
    const float* W1   = (const float*)d_in[2];
    const float* b1   = (const float*)d_in[3];
    const float* W2   = (const float*)d_in[4];
    const float* b2   = (const float*)d_in[5];
    const float* W3   = (const float*)d_in[6];
    const float* b3   = (const float*)d_in[7];
    float* out = (float*)d_out;

    const int Nn = in_sizes[0] / 256;
    const int blocks = (Nn + 127) / 128;

    const int setup_work = 512 * 256 + 512 * 512 + 128 * 512 + out_size;
    setup_weights<<<(setup_work + 255) / 256, 256>>>(W1, W2, W3, out, out_size);

    const int smemA = 128 * XS_LD * 2 + 2 * T256 * 2;                    // 141,312
    const int smemB = 2 * STG * 2 + 4 * T128 * 2 + 2 * T128 * 2 + 512;   // 221,696
    cudaFuncSetAttribute(gemm1_kernel,  cudaFuncAttributeMaxDynamicSharedMemorySize, smemA);
    cudaFuncSetAttribute(gemm23_kernel, cudaFuncAttributeMaxDynamicSharedMemorySize, smemB);

    gemm1_kernel<<<blocks, 512, smemA>>>(X, b1, Nn);
    gemm23_kernel<<<blocks, 512, smemB>>>(gidx, b2, b3, out, Nn);
}

// round 17
// speedup vs baseline: 1.2563x; 1.0598x over previous
#include <cuda_runtime.h>
#include <cuda_fp16.h>
#include <mma.h>
#include <math.h>
#include <cstdint>

using namespace nvcuda;

// ============================================================================
// Pure fp16 WMMA fused MLP + segment sum. 512 threads, warp tile 32x64,
// N-chunks of 256, cp.async single-sync pipelined mainloops, W3 double-
// buffered, next-mc prefetch under GEMM3, 4-strip segment reduce.
// R17: kernel-A full-width fbuf (single-pass epilogue) + half2/float2
// vectorized epilogue loops.
// ============================================================================

#define NODES_PAD (3907 * 128)
#define XS_LD  264             // 256 + 8 pad (fp16 elems)
#define WT_LD  72              // 64 + 8 pad
#define T128   (128 * WT_LD)   // [128x64] tile elems (18,432 B)
#define T256   (256 * WT_LD)   // [256x64] tile elems (36,864 B)
#define STG    (T128 + T256)   // kernel-B GEMM2 stage elems
#define FB_LD  132             // kernel-B fbuf fp32 ld (128 cols)
#define FBA_LD 264             // kernel-A full-width fbuf fp32 ld (256 cols)

__device__ __align__(16) __half g_W1t[512 * 256];
__device__ __align__(16) __half g_W2t[512 * 512];
__device__ __align__(16) __half g_W3t[128 * 512];
__device__ __align__(16) __half g_H1[(size_t)NODES_PAD * 512];

__device__ __forceinline__ void cpa16(uint32_t dst, const void* src) {
    asm volatile("cp.async.cg.shared.global [%0], [%1], 16;" :: "r"(dst), "l"(src));
}
#define CPA_COMMIT() asm volatile("cp.async.commit_group;" ::: "memory")
#define CPA_WAIT0()  asm volatile("cp.async.wait_group 0;" ::: "memory")

// -------- setup: transpose weights to fp16 + zero output (merged) --------
__global__ void setup_weights(const float* __restrict__ W1, const float* __restrict__ W2,
                              const float* __restrict__ W3, float* __restrict__ out,
                              int out_n)
{
    int i = blockIdx.x * blockDim.x + threadIdx.x;
    if (i < 512 * 256) {
        int n = i >> 8, k = i & 255;
        g_W1t[n * 256 + k] = __float2half_rn(W1[k * 512 + n]);
        return;
    }
    i -= 512 * 256;
    if (i < 512 * 512) {
        int n = i >> 9, k = i & 511;
        g_W2t[n * 512 + k] = __float2half_rn(W2[k * 512 + n]);
        return;
    }
    i -= 512 * 512;
    if (i < 128 * 512) {
        int n = i >> 9, k = i & 511;
        g_W3t[n * 512 + k] = __float2half_rn(W3[k * 128 + n]);
        return;
    }
    i -= 128 * 512;
    if (i < out_n) out[i] = 0.f;
}

// ============================================================================
// Kernel A: H1 = relu(X @ W1 + b1).  512 threads, 2 N-chunks of 256.
// SMEM: Xs [128][264] | SW 2 stages x [256][72] | fbuf [128][264] f32
//       (fbuf aliases SW and extends past it; stages dead at epilogue)
// Total: 67,584 + 73,728 + 61,440(ext) = 202,752 B.
// ============================================================================
__global__ void __launch_bounds__(512, 1)
gemm1_kernel(const float* __restrict__ X, const float* __restrict__ b1, int Nn)
{
    extern __shared__ char smem[];
    __half* Xs = (__half*)smem;                       // 67,584 B
    __half* SW = Xs + 128 * XS_LD;                    // 2 x 36,864 B
    float*  fbuf = (float*)SW;                        // [128][264] f32, spans SW+ext
    const uint32_t swu = (uint32_t)__cvta_generic_to_shared(SW);

    const int t   = threadIdx.x;
    const int wid = t >> 5;
    const int wm  = wid & 3;          // 4 warps over M (32 rows each)
    const int wn  = wid >> 2;         // 4 warps over N (64 cols each)
    const int row0 = blockIdx.x * 128;

    auto prefW = [&](int nc, int kt, int b) {         // W1t tile [256n][64k]
        const uint32_t base = swu + (uint32_t)b * T256 * 2;
        #pragma unroll
        for (int p = 0; p < 4; ++p) {
            int idx = t + p * 512;
            int r = idx >> 3, c8 = idx & 7;
            cpa16(base + (uint32_t)(r * WT_LD + c8 * 8) * 2,
                  g_W1t + (size_t)(nc * 256 + r) * 256 + kt * 64 + c8 * 8);
        }
    };

    // first W1 tile in flight while X loads/converts
    prefW(0, 0, 0); CPA_COMMIT();

    // ---- load X (128 x 256 fp32) -> fp16 ----
    #pragma unroll 4
    for (int p = 0; p < 16; ++p) {
        int idx = t + p * 512;
        int r = idx >> 6, c4 = idx & 63;
        float4 v = (row0 + r < Nn) ? *(const float4*)(X + (size_t)(row0 + r) * 256 + c4 * 4)
                                   : make_float4(0.f, 0.f, 0.f, 0.f);
        __half2* d = (__half2*)(Xs + r * XS_LD + c4 * 4);
        d[0] = __floats2half2_rn(v.x, v.y);
        d[1] = __floats2half2_rn(v.z, v.w);
    }
    __syncthreads();

    for (int nc = 0; nc < 2; ++nc) {
        wmma::fragment<wmma::accumulator, 16, 16, 16, float> acc[2][4];
        #pragma unroll
        for (int i = 0; i < 2; ++i)
            #pragma unroll
            for (int j = 0; j < 4; ++j) wmma::fill_fragment(acc[i][j], 0.f);

        if (nc > 0) { prefW(nc, 0, 0); CPA_COMMIT(); }
        for (int kt = 0; kt < 4; ++kt) {              // single-sync pipelined
            CPA_WAIT0();
            __syncthreads();                          // data kt ready; kt-1 compute done
            if (kt < 3) { prefW(nc, kt + 1, (kt + 1) & 1); CPA_COMMIT(); }
            const __half* Wb = SW + (kt & 1) * T256;
            #pragma unroll
            for (int ks = 0; ks < 4; ++ks) {
                wmma::fragment<wmma::matrix_a, 16, 16, 16, __half, wmma::row_major> a[2];
                wmma::fragment<wmma::matrix_b, 16, 16, 16, __half, wmma::col_major> b[4];
                #pragma unroll
                for (int i = 0; i < 2; ++i)
                    wmma::load_matrix_sync(a[i], Xs + (wm * 32 + i * 16) * XS_LD + kt * 64 + ks * 16, XS_LD);
                #pragma unroll
                for (int j = 0; j < 4; ++j)
                    wmma::load_matrix_sync(b[j], Wb + (wn * 64 + j * 16) * WT_LD + ks * 16, WT_LD);
                #pragma unroll
                for (int i = 0; i < 2; ++i)
                    #pragma unroll
                    for (int j = 0; j < 4; ++j)
                        wmma::mma_sync(acc[i][j], a[i], b[j], acc[i][j]);
            }
        }
        __syncthreads();                              // all compute done before fbuf alias

        // ---- single-pass epilogue: all 16 warps store 256 cols at once ----
        #pragma unroll
        for (int i = 0; i < 2; ++i)
            #pragma unroll
            for (int j = 0; j < 4; ++j)
                wmma::store_matrix_sync(fbuf + (wm * 32 + i * 16) * FBA_LD + wn * 64 + j * 16,
                                        acc[i][j], FBA_LD, wmma::mem_row_major);
        __syncthreads();
        const int col0 = nc * 256;
        #pragma unroll 4
        for (int p = 0; p < 32; ++p) {                // 128x256 as half2 pairs
            int idx = t + p * 512;
            int r = idx >> 7, c2 = idx & 127;
            int c = c2 * 2;
            if (row0 + r < Nn) {
                float v0 = fbuf[r * FBA_LD + c]     + b1[col0 + c];
                float v1 = fbuf[r * FBA_LD + c + 1] + b1[col0 + c + 1];
                v0 = v0 > 0.f ? v0 : 0.f;
                v1 = v1 > 0.f ? v1 : 0.f;
                *(__half2*)(g_H1 + (size_t)(row0 + r) * 512 + col0 + c) = __floats2half2_rn(v0, v1);
            }
        }
        __syncthreads();
    }
}

// ============================================================================
// Kernel B: 2 N-chunks of 256. 512 threads.
// SMEM: SG 2 stages x (Hs [128][72] + W2s [256][72]) | Ps 4 x [128][72] |
//       W3s 2 x [128][72] | gids.  fbuf [128][132] f32 aliases SG.
// ============================================================================
__global__ void __launch_bounds__(512, 1)
gemm23_kernel(const int* __restrict__ gidx,
              const float* __restrict__ b2, const float* __restrict__ b3,
              float* __restrict__ out, int Nn)
{
    extern __shared__ char smem[];
    __half* SG  = (__half*)smem;                 // 2 x STG
    __half* Ps  = SG + 2 * STG;                  // 4 k-subtiles [128][72]
    __half* W3s = Ps + 4 * T128;                 // 2 bufs [128][72]
    int*    gids = (int*)(W3s + 2 * T128);
    float*  fbuf = (float*)SG;                   // alias (stages dead at use)
    const uint32_t sgu = (uint32_t)__cvta_generic_to_shared(SG);
    const uint32_t w3u = (uint32_t)__cvta_generic_to_shared(W3s);

    const int t   = threadIdx.x;
    const int wid = t >> 5;
    const int wm  = wid & 3;
    const int wn  = wid >> 2;                    // 0..3
    const int row0 = blockIdx.x * 128;

    if (t < 128) gids[t] = (row0 + t < Nn) ? gidx[row0 + t] : -1;

    auto prefG2 = [&](int mc, int kt, int b) {
        const uint32_t base = sgu + (uint32_t)b * STG * 2;
        #pragma unroll
        for (int p = 0; p < 2; ++p) {            // Hs [128][64]
            int idx = t + p * 512;
            int r = idx >> 3, c8 = idx & 7;
            cpa16(base + (uint32_t)(r * WT_LD + c8 * 8) * 2,
                  g_H1 + (size_t)(row0 + r) * 512 + kt * 64 + c8 * 8);
        }
        #pragma unroll
        for (int p = 0; p < 4; ++p) {            // W2s [256][64]
            int idx = t + p * 512;
            int r = idx >> 3, c8 = idx & 7;
            cpa16(base + (uint32_t)T128 * 2 + (uint32_t)(r * WT_LD + c8 * 8) * 2,
                  g_W2t + (size_t)(mc * 256 + r) * 512 + kt * 64 + c8 * 8);
        }
    };
    auto prefW3 = [&](int mc, int kt3, int b) {  // W3t tile [128n][64k]
        const uint32_t base = w3u + (uint32_t)b * T128 * 2;
        #pragma unroll
        for (int p = 0; p < 2; ++p) {
            int idx = t + p * 512;
            int r = idx >> 3, c8 = idx & 7;
            cpa16(base + (uint32_t)(r * WT_LD + c8 * 8) * 2,
                  g_W3t + (size_t)r * 512 + mc * 256 + kt3 * 64 + c8 * 8);
        }
    };

    wmma::fragment<wmma::accumulator, 16, 16, 16, float> Y[2][2];
    #pragma unroll
    for (int i = 0; i < 2; ++i)
        #pragma unroll
        for (int j = 0; j < 2; ++j) wmma::fill_fragment(Y[i][j], 0.f);

    prefG2(0, 0, 0); CPA_COMMIT();               // initial (mc=0) prefetch

    for (int mc = 0; mc < 2; ++mc) {
        wmma::fragment<wmma::accumulator, 16, 16, 16, float> acc2[2][4];
        #pragma unroll
        for (int i = 0; i < 2; ++i)
            #pragma unroll
            for (int j = 0; j < 4; ++j) wmma::fill_fragment(acc2[i][j], 0.f);

        // ---- GEMM2 chunk, single-sync pipelined, kt = 0..7 ----
        for (int kt = 0; kt < 8; ++kt) {
            CPA_WAIT0();
            __syncthreads();                      // data kt ready; kt-1 compute done
            if (kt < 7) { prefG2(mc, kt + 1, (kt + 1) & 1); CPA_COMMIT(); }
            const __half* Hs  = SG + (kt & 1) * STG;
            const __half* W2s = Hs + T128;
            #pragma unroll
            for (int ks = 0; ks < 4; ++ks) {
                wmma::fragment<wmma::matrix_a, 16, 16, 16, __half, wmma::row_major> a[2];
                wmma::fragment<wmma::matrix_b, 16, 16, 16, __half, wmma::col_major> b[4];
                #pragma unroll
                for (int i = 0; i < 2; ++i)
                    wmma::load_matrix_sync(a[i], Hs + (wm * 32 + i * 16) * WT_LD + ks * 16, WT_LD);
                #pragma unroll
                for (int j = 0; j < 4; ++j)
                    wmma::load_matrix_sync(b[j], W2s + (wn * 64 + j * 16) * WT_LD + ks * 16, WT_LD);
                #pragma unroll
                for (int i = 0; i < 2; ++i)
                    #pragma unroll
                    for (int j = 0; j < 4; ++j)
                        wmma::mma_sync(acc2[i][j], a[i], b[j], acc2[i][j]);
            }
        }
        prefW3(mc, 0, 0); CPA_COMMIT();           // overlaps chunk epilogue
        __syncthreads();                          // compute done before fbuf (aliases SG)

        // ---- chunk epilogue: two 128-col passes -> Ps (fp16, half2) ----
        #pragma unroll 1
        for (int h = 0; h < 2; ++h) {
            if ((wn >> 1) == h) {
                #pragma unroll
                for (int i = 0; i < 2; ++i)
                    #pragma unroll
                    for (int j = 0; j < 4; ++j)
                        wmma::store_matrix_sync(fbuf + (wm * 32 + i * 16) * FB_LD + (wn & 1) * 64 + j * 16,
                                                acc2[i][j], FB_LD, wmma::mem_row_major);
            }
            __syncthreads();
            #pragma unroll 4
            for (int p = 0; p < 16; ++p) {        // 128x128 as half2 pairs
                int idx = t + p * 512;
                int r = idx >> 6, c2 = idx & 63;
                int c = c2 * 2;
                float v0 = fbuf[r * FB_LD + c]     + b2[mc * 256 + h * 128 + c];
                float v1 = fbuf[r * FB_LD + c + 1] + b2[mc * 256 + h * 128 + c + 1];
                v0 = v0 > 0.f ? v0 : 0.f;
                v1 = v1 > 0.f ? v1 : 0.f;
                int sub = h * 2 + (c >> 6);
                *(__half2*)(Ps + sub * T128 + r * WT_LD + (c & 63)) = __floats2half2_rn(v0, v1);
            }
            __syncthreads();
        }

        // next-mc GEMM2 tiles prefetched under GEMM3 (SG/fbuf now dead)
        if (mc < 1) { prefG2(mc + 1, 0, 0); CPA_COMMIT(); }

        // ---- GEMM3 partial: Y += Ps (128x256) @ W3t[:, mc*256..+256] ----
        for (int kt3 = 0; kt3 < 4; ++kt3) {       // single-sync pipelined
            CPA_WAIT0();
            __syncthreads();
            if (kt3 < 3) { prefW3(mc, kt3 + 1, (kt3 + 1) & 1); CPA_COMMIT(); }
            const __half* Wb = W3s + (kt3 & 1) * T128;
            const __half* Pb = Ps + kt3 * T128;
            #pragma unroll
            for (int ks = 0; ks < 4; ++ks) {
                wmma::fragment<wmma::matrix_a, 16, 16, 16, __half, wmma::row_major> a[2];
                wmma::fragment<wmma::matrix_b, 16, 16, 16, __half, wmma::col_major> b[2];
                #pragma unroll
                for (int i = 0; i < 2; ++i)
                    wmma::load_matrix_sync(a[i], Pb + (wm * 32 + i * 16) * WT_LD + ks * 16, WT_LD);
                #pragma unroll
                for (int j = 0; j < 2; ++j)
                    wmma::load_matrix_sync(b[j], Wb + (wn * 32 + j * 16) * WT_LD + ks * 16, WT_LD);
                #pragma unroll
                for (int i = 0; i < 2; ++i)
                    #pragma unroll
                    for (int j = 0; j < 2; ++j)
                        wmma::mma_sync(Y[i][j], a[i], b[j], Y[i][j]);
            }
        }
        __syncthreads();                          // GEMM3 done before Ps reuse next mc
    }

    // ---- final: Y -> fbuf, +b3, silu (float2), 4-strip segment reduce ----
    #pragma unroll
    for (int i = 0; i < 2; ++i)
        #pragma unroll
        for (int j = 0; j < 2; ++j)
            wmma::store_matrix_sync(fbuf + (wm * 32 + i * 16) * FB_LD + wn * 32 + j * 16,
                                    Y[i][j], FB_LD, wmma::mem_row_major);
    __syncthreads();
    #pragma unroll 4
    for (int p = 0; p < 16; ++p) {
        int idx = t + p * 512;
        int r = idx >> 6, c2 = idx & 63;
        int c = c2 * 2;
        float2 yv = *(float2*)(fbuf + r * FB_LD + c);
        float y0 = yv.x + b3[c];
        float y1 = yv.y + b3[c + 1];
        yv.x = y0 / (1.f + expf(-y0));
        yv.y = y1 / (1.f + expf(-y1));
        *(float2*)(fbuf + r * FB_LD + c) = yv;
    }
    __syncthreads();

    {
        const int s = t >> 7, c = t & 127;        // 4 row-strips x 128 cols
        const int rbeg = s * 32, rend = rbeg + 32;
        int cur = gids[rbeg];
        float sum = 0.f;
        #pragma unroll 1
        for (int r = rbeg; r < rend; ++r) {
            int gi = gids[r];
            if (gi != cur) {
                if (cur >= 0) atomicAdd(&out[(size_t)cur * 128 + c], sum);
                cur = gi; sum = 0.f;
            }
            if (gi >= 0) sum += fbuf[r * FB_LD + c];
        }
        if (cur >= 0) atomicAdd(&out[(size_t)cur * 128 + c], sum);
    }
}

// ============================================================================
extern "C" void kernel_launch(void* const* d_in, const int* in_sizes, int n_in,
                              void* d_out, int out_size)
{
    const float* X    = (const float*)d_in[0];
    const int*   gidx = (const int*)d_in[1];     // int32 (JAX x64 disabled)
    const float* W1   = (const float*)d_in[2];
    const float* b1   = (const float*)d_in[3];
    const float* W2   = (const float*)d_in[4];
    const float* b2   = (const float*)d_in[5];
    const float* W3   = (const float*)d_in[6];
    const float* b3   = (const float*)d_in[7];
    float* out = (float*)d_out;

    const int Nn = in_sizes[0] / 256;
    const int blocks = (Nn + 127) / 128;

    const int setup_work = 512 * 256 + 512 * 512 + 128 * 512 + out_size;
    setup_weights<<<(setup_work + 255) / 256, 256>>>(W1, W2, W3, out, out_size);

    // kernel A: Xs 67,584 + max(SW 73,728, fbuf 135,168 aliased at SW) = 202,752
    const int smemA = 128 * XS_LD * 2 + 128 * FBA_LD * 4;                // 202,752
    const int smemB = 2 * STG * 2 + 4 * T128 * 2 + 2 * T128 * 2 + 512;   // 221,696
    cudaFuncSetAttribute(gemm1_kernel,  cudaFuncAttributeMaxDynamicSharedMemorySize, smemA);
    cudaFuncSetAttribute(gemm23_kernel, cudaFuncAttributeMaxDynamicSharedMemorySize, smemB);

    gemm1_kernel<<<blocks, 512, smemA>>>(X, b1, Nn);
    gemm23_kernel<<<blocks, 512, smemB>>>(gidx, b2, b3, out, Nn);
}